// round 8
// baseline (speedup 1.0000x reference)
#include <cuda_runtime.h>
#include <cuda_fp16.h>
#include <cstdint>

// N=2048, F_IN=128, F_OUT=64
//   H = X@W + b
//   out[j,f] = sum_k mf[j,k]*H[k,f]* (sum_i A[j,i]*H[i,f]*mh[i,k])
// Per f: G_f = A . diag(h_f) . mh  (fp16 mma.sync, fp32 accum), k contracted
// immediately in the epilogue. mh pre-transposed fp16 [k][i]; B frags via
// ldmatrix.x4; H folded via HMUL2.
// R8: FB=2 -> 64 acc regs, __launch_bounds__(256,2) -> 2 CTAs/SM so stalls in
// one CTA (barriers/prologue/epilogue) are covered by the other CTA's warps.
// IC=64, 4-stage ring (race-free), 99328 B smem per CTA (2 fit in 228KB).

#define NN   2048
#define FIN  128
#define FOUT 64

#define JT 128
#define KT 64
#define FB 2
#define IC 64
#define NCHUNK (NN / IC)   // 32

// ---- smem: 4 stages of {A fp16 swizzled, mhT fp16 swizzled, Hh fp16} ----
#define ST_A   0        // [128 j][64 i] fp16, 128B rows, XOR16 swizzle = 16384
#define ST_MH  16384    // [64 k][64 i] fp16                           = 8192
#define ST_H   24576    // [2 f][64 i] fp16                            = 256
#define STAGE  24832
#define NSTG   4
#define MF_ST  76       // epilogue mf stride (fp32 words)
#define EP_HK  (128 * MF_ST * 4)        // 38912
#define SMEM_TOTAL (NSTG * STAGE)       // 99328

__device__ float  g_H[NN * FOUT];          // fp32 H for epilogue
__device__ __half g_HhT[FOUT * NN];        // fp16 H transposed [f][i]
__device__ __half g_Ah[(size_t)NN * NN];   // adjacency fp16 [j][i]
__device__ __half g_mhT[(size_t)NN * NN];  // mask_hadamard fp16 transposed [k][i]

// ---------------- helpers ----------------
__device__ __forceinline__ uint32_t smem_to_u32(const void* p) {
    uint32_t a;
    asm("{ .reg .u64 t; cvta.to.shared.u64 t, %1; cvt.u32.u64 %0, t; }"
        : "=r"(a) : "l"(p));
    return a;
}
__device__ __forceinline__ void cp16(uint32_t dst, const void* src) {
    asm volatile("cp.async.cg.shared.global [%0], [%1], 16;" :: "r"(dst), "l"(src));
}
__device__ __forceinline__ void cp_commit() {
    asm volatile("cp.async.commit_group;" ::: "memory");
}
__device__ __forceinline__ uint32_t lds32(uint32_t addr) {
    uint32_t v;
    asm volatile("ld.shared.b32 %0, [%1];" : "=r"(v) : "r"(addr));
    return v;
}
__device__ __forceinline__ void ldm4(uint32_t* r, uint32_t addr) {
    asm volatile("ldmatrix.sync.aligned.m8n8.x4.shared.b16 {%0,%1,%2,%3}, [%4];"
                 : "=r"(r[0]), "=r"(r[1]), "=r"(r[2]), "=r"(r[3]) : "r"(addr));
}
__device__ __forceinline__ uint32_t hmul2u(uint32_t a, uint32_t b) {
    __half2 r = __hmul2(*(__half2*)&a, *(__half2*)&b);
    return *(uint32_t*)&r;
}
__device__ __forceinline__ void mma16816(float* c, const uint32_t* a,
                                         uint32_t b0, uint32_t b1) {
    asm volatile(
        "mma.sync.aligned.m16n8k16.row.col.f32.f16.f16.f32 "
        "{%0,%1,%2,%3}, {%4,%5,%6,%7}, {%8,%9}, {%0,%1,%2,%3};"
        : "+f"(c[0]), "+f"(c[1]), "+f"(c[2]), "+f"(c[3])
        : "r"(a[0]), "r"(a[1]), "r"(a[2]), "r"(a[3]), "r"(b0), "r"(b1));
}

// ---------------- prep ----------------
__global__ void prep_H(const float* __restrict__ X, const float* __restrict__ W,
                       const float* __restrict__ bias) {
    int id = blockIdx.x * blockDim.x + threadIdx.x;  // 131072
    int i = id >> 6, f = id & 63;
    float s = 0.f;
#pragma unroll 8
    for (int c = 0; c < FIN; c++) s += X[i * FIN + c] * W[c * FOUT + f];
    s += bias[f];
    g_H[id] = s;
    g_HhT[f * NN + i] = __float2half_rn(s);
}
__global__ void prep_A(const float* __restrict__ A) {
    size_t id = (size_t)blockIdx.x * blockDim.x + threadIdx.x;
    float2 v = ((const float2*)A)[id];
    ((__half2*)g_Ah)[id] = __floats2half2_rn(v.x, v.y);
}
// tiled transpose + fp16 convert: g_mhT[k][i] = fp16(mh[i][k])
__global__ void prep_mhT(const float* __restrict__ mh) {
    __shared__ float t[32][33];
    const int bx = blockIdx.x * 32, by = blockIdx.y * 32;  // bx: k, by: i
    const int tx = threadIdx.x & 31, ty = threadIdx.x >> 5;
#pragma unroll
    for (int y = ty; y < 32; y += 8)
        t[y][tx] = mh[(size_t)(by + y) * NN + bx + tx];
    __syncthreads();
#pragma unroll
    for (int o = 0; o < 2; o++) {
        int idx = threadIdx.x + o * 256;
        int kr = idx >> 4, ip = idx & 15;
        __half2 v = __floats2half2_rn(t[ip * 2][kr], t[ip * 2 + 1][kr]);
        *(__half2*)&g_mhT[(size_t)(bx + kr) * NN + by + ip * 2] = v;
    }
}
__global__ void zero_out(float* __restrict__ out) {
    out[blockIdx.x * blockDim.x + threadIdx.x] = 0.f;
}

// ---------------- main ----------------
// grid (16 jt, 32 kt, 32 f-pairs), 256 threads = 8 warps, 2 (j) x 4 (k).
// 2 CTAs per SM (launch_bounds), so the scheduler interleaves independent CTAs.
__global__ void __launch_bounds__(256, 2)
interaction_main(const float* __restrict__ mf, float* __restrict__ out) {
    extern __shared__ char smem[];
    const uint32_t sb = smem_to_u32(smem);
    const int tid = threadIdx.x;
    const int lane = tid & 31, wid = tid >> 5;
    const int g = lane >> 2, tg = lane & 3;
    const int jbase = blockIdx.x * JT;
    const int kb0 = blockIdx.y * KT;
    const int f0 = blockIdx.z * FB;
    const int jbw = (wid & 1) * 64;    // warp j block (4 x m16)
    const int kbw = (wid >> 1) * 16;   // warp k block (2 x n8)

    float acc[FB][4][2][4];            // 64 regs
#pragma unroll
    for (int f = 0; f < FB; f++)
#pragma unroll
        for (int mt = 0; mt < 4; mt++)
#pragma unroll
            for (int nt = 0; nt < 2; nt++)
#pragma unroll
                for (int c = 0; c < 4; c++) acc[f][mt][nt][c] = 0.f;

    // B ldmatrix lane mapping (validated R5): tile id = lane>>3,
    // bit0 -> i-half (col +16B), bit1 -> n8 tile (row group +8)
    const int btl = lane >> 3, brr = lane & 7;
    const int bn = kbw + ((btl >> 1) & 1) * 8 + brr;
    const uint32_t bcol0 = (uint32_t)((btl & 1) * 16);

    // ---- chunk loader: A 1024 cp16, mh 512 cp16, h 16 cp16 ----
    auto issue = [&](int c, int st) {
        const uint32_t base = sb + st * STAGE;
        const int ibase = c * IC;
#pragma unroll
        for (int o = 0; o < 4; o++) {
            int idx = tid + o * 256, j = idx >> 3, cc = idx & 7;
            cp16(base + ST_A + j * 128 + ((cc * 16) ^ ((j & 7) * 16)),
                 g_Ah + (size_t)(jbase + j) * NN + ibase + cc * 8);
        }
#pragma unroll
        for (int o = 0; o < 2; o++) {
            int idx = tid + o * 256, n = idx >> 3, cc = idx & 7;
            cp16(base + ST_MH + n * 128 + ((cc * 16) ^ ((n & 7) * 16)),
                 g_mhT + (size_t)(kb0 + n) * NN + ibase + cc * 8);
        }
        if (tid < 16) {
            int f = tid >> 3, cc = tid & 7;
            cp16(base + ST_H + f * 128 + cc * 16,
                 g_HhT + (size_t)(f0 + f) * NN + ibase + cc * 8);
        }
        cp_commit();
    };

    issue(0, 0);
    issue(1, 1);

    for (int c = 0; c < NCHUNK; c++) {
        const int st = c & 3;
        if (c + 2 < NCHUNK) {
            issue(c + 2, (c + 2) & 3);
            asm volatile("cp.async.wait_group 2;" ::: "memory");
        } else if (c + 1 < NCHUNK) {
            asm volatile("cp.async.wait_group 1;" ::: "memory");
        } else {
            asm volatile("cp.async.wait_group 0;" ::: "memory");
        }
        __syncthreads();  // single barrier per chunk; 4-stage ring: next iter's
                          // issue targets (c+3)&3 which no warp past this
                          // barrier still reads (stages c..c+2 distinct).

        const uint32_t abase = sb + st * STAGE + ST_A;
        const uint32_t mbase = sb + st * STAGE + ST_MH;
        const uint32_t hbase = sb + st * STAGE + ST_H;

#pragma unroll
        for (int ks = 0; ks < 4; ks++) {
            uint32_t a[4][4];
#pragma unroll
            for (int mt = 0; mt < 4; mt++) {
                int jr = jbw + mt * 16 + (lane & 15);
                ldm4(a[mt], abase + jr * 128 +
                               ((((lane >> 4) * 16) + ks * 32) ^ ((jr & 7) * 16)));
            }
            uint32_t bfr[4];
            ldm4(bfr, mbase + bn * 128 + ((ks * 32 + bcol0) ^ ((bn & 7) * 16)));

#pragma unroll
            for (int f = 0; f < FB; f++) {
                uint32_t hA = lds32(hbase + f * 128 + ks * 32 + tg * 4);
                uint32_t hB = lds32(hbase + f * 128 + ks * 32 + tg * 4 + 16);
                uint32_t b00 = hmul2u(bfr[0], hA);
                uint32_t b01 = hmul2u(bfr[1], hB);
                uint32_t b10 = hmul2u(bfr[2], hA);
                uint32_t b11 = hmul2u(bfr[3], hB);
#pragma unroll
                for (int mt = 0; mt < 4; mt++) {
                    mma16816(acc[f][mt][0], a[mt], b00, b01);
                    mma16816(acc[f][mt][1], a[mt], b10, b11);
                }
            }
        }
        // no trailing barrier (4-stage ring safety)
    }
    __syncthreads();  // all compute done before epilogue overwrites smem

    // ---- epilogue: out[j,f] += sum_k acc * mf[j,k] * H[k,f] ----
    float* mfs = (float*)smem;               // [128][MF_ST] fp32 = 38912 B
    float* Hk  = (float*)(smem + EP_HK);     // [64][2] fp32 (past mf tile)
#pragma unroll
    for (int o = 0; o < 32; o++) {
        int idx = tid + o * 256, r = idx >> 6, cc = idx & 63;
        mfs[r * MF_ST + cc] = mf[(size_t)(jbase + r) * NN + kb0 + cc];
    }
    if (tid < 128) {
        int kk = tid >> 1, ff = tid & 1;
        Hk[kk * 2 + ff] = g_H[(kb0 + kk) * FOUT + f0 + ff];
    }
    __syncthreads();

#pragma unroll
    for (int f = 0; f < FB; f++)
#pragma unroll
        for (int mt = 0; mt < 4; mt++)
#pragma unroll
            for (int h2 = 0; h2 < 2; h2++) {
                int j = jbw + mt * 16 + g + 8 * h2;
                float s = 0.f;
#pragma unroll
                for (int nt = 0; nt < 2; nt++)
#pragma unroll
                    for (int e = 0; e < 2; e++) {
                        int k = kbw + nt * 8 + tg * 2 + e;
                        s += acc[f][mt][nt][h2 * 2 + e] * mfs[j * MF_ST + k] *
                             Hk[k * 2 + f];
                    }
                s += __shfl_xor_sync(0xffffffffu, s, 1);
                s += __shfl_xor_sync(0xffffffffu, s, 2);
                if (tg == 0)
                    atomicAdd(&out[(size_t)(jbase + j) * FOUT + f0 + f], s);
            }
}

// ---------------- launch ----------------
extern "C" void kernel_launch(void* const* d_in, const int* in_sizes, int n_in,
                              void* d_out, int out_size) {
    const float* X  = (const float*)d_in[0];
    const float* A  = (const float*)d_in[1];
    const float* mf = (const float*)d_in[2];
    const float* mh = (const float*)d_in[3];
    const float* W  = (const float*)d_in[4];
    const float* b  = (const float*)d_in[5];
    float* out = (float*)d_out;

    cudaFuncSetAttribute(interaction_main,
                         cudaFuncAttributeMaxDynamicSharedMemorySize, SMEM_TOTAL);

    prep_H<<<256, 512>>>(X, W, b);
    prep_A<<<4096, 512>>>(A);
    prep_mhT<<<dim3(64, 64), 256>>>(mh);
    zero_out<<<256, 512>>>(out);
    interaction_main<<<dim3(16, 32, 32), 256, SMEM_TOTAL>>>(mf, out);
}

// round 9
// speedup vs baseline: 1.0046x; 1.0046x over previous
#include <cuda_runtime.h>
#include <cuda_fp16.h>
#include <cstdint>

// N=2048, F_IN=128, F_OUT=64
//   H = X@W + b
//   out[j,f] = sum_k mf[j,k]*H[k,f]* (sum_i A[j,i]*H[i,f]*mh[i,k])
// Per f: G_f = A . diag(h_f) . mh  (fp16 mma.sync, fp32 accum), k contracted
// immediately in the epilogue. mh pre-transposed fp16 [k][i]; B frags via
// ldmatrix.x4; H folded via HMUL2.
// R9: PERSISTENT CTAs (grid = #SMs). Each CTA walks tiles t = cta + s*nsm
// (fq fastest -> 16 consecutive tiles share A/mh in L2). The 3-stage cp.async
// ring runs continuously across tile boundaries (global chunk counter), so
// prologue is paid once and epilogues overlap with prefetched next-tile loads.
// Epilogue reads mf directly from gmem (L2-hot); Hk double-buffered by tile
// parity via cp.async bundled with each tile's chunk-0 group.

#define NN   2048
#define FIN  128
#define FOUT 64

#define JT 128
#define KT 64
#define FB 4
#define IC 128
#define CPT 16            // chunks per tile
#define NTILES 8192       // 16 jt * 32 kt * 16 fq

// ---- smem: 3 ring stages {A, mhT, Hh} + parity Hk ----
#define ST_A   0          // [128 j][128 i] fp16, 256B rows, XOR16 swz = 32768
#define ST_MH  32768      // [64 k][128 i] fp16                       = 16384
#define ST_H   49152      // [4 f][128 i] fp16                        = 1024
#define STAGE  50176
#define NSTG   3
#define SM_HK  (NSTG * STAGE)          // 150528; 2 x [64][4] fp32 = 2048
#define SMEM_TOTAL (SM_HK + 2048)      // 152576

__device__ float  g_H[NN * FOUT];          // fp32 H for epilogue
__device__ __half g_HhT[FOUT * NN];        // fp16 H transposed [f][i]
__device__ __half g_Ah[(size_t)NN * NN];   // adjacency fp16 [j][i]
__device__ __half g_mhT[(size_t)NN * NN];  // mask_hadamard fp16 transposed [k][i]

// ---------------- helpers ----------------
__device__ __forceinline__ uint32_t smem_to_u32(const void* p) {
    uint32_t a;
    asm("{ .reg .u64 t; cvta.to.shared.u64 t, %1; cvt.u32.u64 %0, t; }"
        : "=r"(a) : "l"(p));
    return a;
}
__device__ __forceinline__ void cp16(uint32_t dst, const void* src) {
    asm volatile("cp.async.cg.shared.global [%0], [%1], 16;" :: "r"(dst), "l"(src));
}
__device__ __forceinline__ void cp_commit() {
    asm volatile("cp.async.commit_group;" ::: "memory");
}
__device__ __forceinline__ uint32_t lds32(uint32_t addr) {
    uint32_t v;
    asm volatile("ld.shared.b32 %0, [%1];" : "=r"(v) : "r"(addr));
    return v;
}
__device__ __forceinline__ void ldm4(uint32_t* r, uint32_t addr) {
    asm volatile("ldmatrix.sync.aligned.m8n8.x4.shared.b16 {%0,%1,%2,%3}, [%4];"
                 : "=r"(r[0]), "=r"(r[1]), "=r"(r[2]), "=r"(r[3]) : "r"(addr));
}
__device__ __forceinline__ uint32_t hmul2u(uint32_t a, uint32_t b) {
    __half2 r = __hmul2(*(__half2*)&a, *(__half2*)&b);
    return *(uint32_t*)&r;
}
__device__ __forceinline__ void mma16816(float* c, const uint32_t* a,
                                         uint32_t b0, uint32_t b1) {
    asm volatile(
        "mma.sync.aligned.m16n8k16.row.col.f32.f16.f16.f32 "
        "{%0,%1,%2,%3}, {%4,%5,%6,%7}, {%8,%9}, {%0,%1,%2,%3};"
        : "+f"(c[0]), "+f"(c[1]), "+f"(c[2]), "+f"(c[3])
        : "r"(a[0]), "r"(a[1]), "r"(a[2]), "r"(a[3]), "r"(b0), "r"(b1));
}

// ---------------- prep ----------------
__global__ void prep_H(const float* __restrict__ X, const float* __restrict__ W,
                       const float* __restrict__ bias) {
    int id = blockIdx.x * blockDim.x + threadIdx.x;  // 131072
    int i = id >> 6, f = id & 63;
    float s = 0.f;
#pragma unroll 8
    for (int c = 0; c < FIN; c++) s += X[i * FIN + c] * W[c * FOUT + f];
    s += bias[f];
    g_H[id] = s;
    g_HhT[f * NN + i] = __float2half_rn(s);
}
__global__ void prep_A(const float* __restrict__ A) {
    size_t id = (size_t)blockIdx.x * blockDim.x + threadIdx.x;
    float2 v = ((const float2*)A)[id];
    ((__half2*)g_Ah)[id] = __floats2half2_rn(v.x, v.y);
}
// tiled transpose + fp16 convert: g_mhT[k][i] = fp16(mh[i][k])
__global__ void prep_mhT(const float* __restrict__ mh) {
    __shared__ float t[32][33];
    const int bx = blockIdx.x * 32, by = blockIdx.y * 32;  // bx: k, by: i
    const int tx = threadIdx.x & 31, ty = threadIdx.x >> 5;
#pragma unroll
    for (int y = ty; y < 32; y += 8)
        t[y][tx] = mh[(size_t)(by + y) * NN + bx + tx];
    __syncthreads();
#pragma unroll
    for (int o = 0; o < 2; o++) {
        int idx = threadIdx.x + o * 256;
        int kr = idx >> 4, ip = idx & 15;
        __half2 v = __floats2half2_rn(t[ip * 2][kr], t[ip * 2 + 1][kr]);
        *(__half2*)&g_mhT[(size_t)(bx + kr) * NN + by + ip * 2] = v;
    }
}
__global__ void zero_out(float* __restrict__ out) {
    out[blockIdx.x * blockDim.x + threadIdx.x] = 0.f;
}

// ---------------- main (persistent) ----------------
// grid = #SMs, 256 threads = 8 warps laid out 2 (j) x 4 (k).
__global__ void __launch_bounds__(256, 1)
interaction_main(const float* __restrict__ mf, float* __restrict__ out) {
    extern __shared__ char smem[];
    const uint32_t sb = smem_to_u32(smem);
    const int tid = threadIdx.x;
    const int lane = tid & 31, wid = tid >> 5;
    const int g = lane >> 2, tg = lane & 3;
    const int jbw = (wid & 1) * 64;    // warp j block (4 x m16)
    const int kbw = (wid >> 1) * 16;   // warp k block (2 x n8)
    const int cta = blockIdx.x, nsm = gridDim.x;

    const int ntiles = (cta < NTILES) ? ((NTILES - 1 - cta) / nsm + 1) : 0;
    const int total = ntiles * CPT;    // total chunks for this CTA
    if (total == 0) return;

    // B ldmatrix lane mapping (validated R5): tile id = lane>>3,
    // bit0 -> i-half (col +16B), bit1 -> n8 tile (row group +8)
    const int btl = lane >> 3;
    const int bn = kbw + ((btl >> 1) & 1) * 8 + (lane & 7);
    const uint32_t bcol0 = (uint32_t)((btl & 1) * 16);

    // ---- chunk loader: tile decoded from global chunk index ----
    auto issue = [&](int gc) {
        if (gc >= total) return;
        const int s = gc >> 4, c = gc & 15;
        const int t = cta + s * nsm;
        const int jb = (t >> 9) * JT;
        const int kb = ((t >> 4) & 31) * KT;
        const int ff = (t & 15) * FB;
        const uint32_t base = sb + (uint32_t)(gc % 3) * STAGE;
        const int ibase = c * IC;
#pragma unroll
        for (int o = 0; o < 8; o++) {
            int idx = tid + o * 256, j = idx >> 4, cc = idx & 15;
            cp16(base + ST_A + j * 256 + ((cc * 16) ^ ((j & 7) * 16)),
                 g_Ah + (size_t)(jb + j) * NN + ibase + cc * 8);
        }
#pragma unroll
        for (int o = 0; o < 4; o++) {
            int idx = tid + o * 256, n = idx >> 4, cc = idx & 15;
            cp16(base + ST_MH + n * 256 + ((cc * 16) ^ ((n & 7) * 16)),
                 g_mhT + (size_t)(kb + n) * NN + ibase + cc * 8);
        }
        if (tid < 64) {
            int f = tid >> 4, cc = tid & 15;
            cp16(base + ST_H + f * 256 + cc * 16,
                 g_HhT + (size_t)(ff + f) * NN + ibase + cc * 8);
        }
        if (c == 0 && tid < 64) {
            // Hk [64][4] fp32 for tile s, parity buffer s&1 (race-free:
            // written >=14 barriers after epilogue of tile s-2 finished)
            cp16(sb + SM_HK + (uint32_t)(s & 1) * 1024 + tid * 16,
                 g_H + (kb + tid) * FOUT + ff);
        }
        cp_commit();
    };

    issue(0);
    issue(1);

    float acc[FB][4][2][4];            // 128 regs
    for (int s = 0; s < ntiles; s++) {
        const int t = cta + s * nsm;
        const int jbase = (t >> 9) * JT;
        const int kb0 = ((t >> 4) & 31) * KT;
        const int f0 = (t & 15) * FB;

#pragma unroll
        for (int f = 0; f < FB; f++)
#pragma unroll
            for (int mt = 0; mt < 4; mt++)
#pragma unroll
                for (int nt = 0; nt < 2; nt++)
#pragma unroll
                    for (int e = 0; e < 4; e++) acc[f][mt][nt][e] = 0.f;

        for (int c = 0; c < CPT; c++) {
            const int gc = s * CPT + c;
            if (gc + 1 < total) {
                asm volatile("cp.async.wait_group 1;" ::: "memory");
            } else {
                asm volatile("cp.async.wait_group 0;" ::: "memory");
            }
            __syncthreads();   // chunk gc visible; all warps aligned
            issue(gc + 2);     // post-barrier: stage (gc+2)%3 has no readers
                               // (all warps hold only gc%3 / (gc+1)%3)

            const int st = gc % 3;
            const uint32_t abase = sb + (uint32_t)st * STAGE + ST_A;
            const uint32_t mbase = sb + (uint32_t)st * STAGE + ST_MH;
            const uint32_t hbase = sb + (uint32_t)st * STAGE + ST_H;

#pragma unroll 4
            for (int ks = 0; ks < 8; ks++) {
                uint32_t a[4][4];
#pragma unroll
                for (int mt = 0; mt < 4; mt++) {
                    int jr = jbw + mt * 16 + (lane & 15);
                    ldm4(a[mt], abase + jr * 256 +
                                   ((((lane >> 4) * 16) + ks * 32) ^ ((jr & 7) * 16)));
                }
                uint32_t bfr[4];
                ldm4(bfr, mbase + bn * 256 + ((ks * 32 + bcol0) ^ ((bn & 7) * 16)));

#pragma unroll
                for (int f = 0; f < FB; f++) {
                    uint32_t hA = lds32(hbase + f * 256 + ks * 32 + tg * 4);
                    uint32_t hB = lds32(hbase + f * 256 + ks * 32 + tg * 4 + 16);
                    uint32_t b00 = hmul2u(bfr[0], hA);
                    uint32_t b01 = hmul2u(bfr[1], hB);
                    uint32_t b10 = hmul2u(bfr[2], hA);
                    uint32_t b11 = hmul2u(bfr[3], hB);
#pragma unroll
                    for (int mt = 0; mt < 4; mt++) {
                        mma16816(acc[f][mt][0], a[mt], b00, b01);
                        mma16816(acc[f][mt][1], a[mt], b10, b11);
                    }
                }
            }
        }

        // ---- epilogue (no barrier): mf via LDG (L2-hot), Hk from parity smem
        const float* Hks = (const float*)(smem + SM_HK + (size_t)(s & 1) * 1024);
#pragma unroll
        for (int mt = 0; mt < 4; mt++)
#pragma unroll
            for (int h2 = 0; h2 < 2; h2++) {
                const int j = jbw + mt * 16 + g + 8 * h2;
                float s4[FB] = {0.f, 0.f, 0.f, 0.f};
#pragma unroll
                for (int nt = 0; nt < 2; nt++)
#pragma unroll
                    for (int e = 0; e < 2; e++) {
                        const int k = kbw + nt * 8 + tg * 2 + e;
                        const float mv =
                            __ldg(&mf[(size_t)(jbase + j) * NN + kb0 + k]);
                        const float4 hk = *(const float4*)&Hks[k * 4];
                        s4[0] += acc[0][mt][nt][h2 * 2 + e] * mv * hk.x;
                        s4[1] += acc[1][mt][nt][h2 * 2 + e] * mv * hk.y;
                        s4[2] += acc[2][mt][nt][h2 * 2 + e] * mv * hk.z;
                        s4[3] += acc[3][mt][nt][h2 * 2 + e] * mv * hk.w;
                    }
#pragma unroll
                for (int f = 0; f < FB; f++) {
                    float v = s4[f];
                    v += __shfl_xor_sync(0xffffffffu, v, 1);
                    v += __shfl_xor_sync(0xffffffffu, v, 2);
                    if (tg == 0)
                        atomicAdd(&out[(size_t)(jbase + j) * FOUT + f0 + f], v);
                }
            }
    }
}

// ---------------- launch ----------------
extern "C" void kernel_launch(void* const* d_in, const int* in_sizes, int n_in,
                              void* d_out, int out_size) {
    const float* X  = (const float*)d_in[0];
    const float* A  = (const float*)d_in[1];
    const float* mf = (const float*)d_in[2];
    const float* mh = (const float*)d_in[3];
    const float* W  = (const float*)d_in[4];
    const float* b  = (const float*)d_in[5];
    float* out = (float*)d_out;

    int dev = 0, nsm = 148;
    cudaGetDevice(&dev);
    cudaDeviceGetAttribute(&nsm, cudaDevAttrMultiProcessorCount, dev);

    cudaFuncSetAttribute(interaction_main,
                         cudaFuncAttributeMaxDynamicSharedMemorySize, SMEM_TOTAL);

    prep_H<<<256, 512>>>(X, W, b);
    prep_A<<<4096, 512>>>(A);
    prep_mhT<<<dim3(64, 64), 256>>>(mh);
    zero_out<<<256, 512>>>(out);
    interaction_main<<<nsm, 256, SMEM_TOTAL>>>(mf, out);
}

// round 10
// speedup vs baseline: 1.0574x; 1.0526x over previous
#include <cuda_runtime.h>
#include <cuda_fp16.h>
#include <cstdint>

// N=2048, F_IN=128, F_OUT=64
//   H = X@W + b
//   out[j,f] = sum_k mf[j,k]*H[k,f]* (sum_i A[j,i]*H[i,f]*mh[i,k])
// Per f: G_f = A . diag(h_f) . mh  (fp16 mma.sync, fp32 accum), k contracted
// immediately in the epilogue. mh pre-transposed fp16 [k][i]; B frags via
// ldmatrix.x4; H folded via HMUL2.
// R10: persistent CTAs (grid=#SMs) WITH the R7 pipeline restored: 4-stage
// cp.async ring, issue(gc+2) BEFORE wait_group 2 (loads in flight during the
// wait). Ring runs continuously across tile boundaries. Epilogue: float2 mf
// LDG (L2-hot), Hk parity smem via cp.async bundled with chunk-0 groups.

#define NN   2048
#define FIN  128
#define FOUT 64

#define JT 128
#define KT 64
#define FB 4
#define IC 128
#define CPT 16            // chunks per tile
#define NTILES 8192       // 16 jt * 32 kt * 16 fq

// ---- smem: 4 ring stages {A, mhT, Hh} + parity Hk ----
#define ST_A   0          // [128 j][128 i] fp16, 256B rows, XOR16 swz = 32768
#define ST_MH  32768      // [64 k][128 i] fp16                       = 16384
#define ST_H   49152      // [4 f][128 i] fp16                        = 1024
#define STAGE  50176
#define NSTG   4
#define SM_HK  (NSTG * STAGE)          // 200704; 2 x [64][4] fp32 = 2048
#define SMEM_TOTAL (SM_HK + 2048)      // 202752

__device__ float  g_H[NN * FOUT];          // fp32 H for epilogue
__device__ __half g_HhT[FOUT * NN];        // fp16 H transposed [f][i]
__device__ __half g_Ah[(size_t)NN * NN];   // adjacency fp16 [j][i]
__device__ __half g_mhT[(size_t)NN * NN];  // mask_hadamard fp16 transposed [k][i]

// ---------------- helpers ----------------
__device__ __forceinline__ uint32_t smem_to_u32(const void* p) {
    uint32_t a;
    asm("{ .reg .u64 t; cvta.to.shared.u64 t, %1; cvt.u32.u64 %0, t; }"
        : "=r"(a) : "l"(p));
    return a;
}
__device__ __forceinline__ void cp16(uint32_t dst, const void* src) {
    asm volatile("cp.async.cg.shared.global [%0], [%1], 16;" :: "r"(dst), "l"(src));
}
__device__ __forceinline__ void cp_commit() {
    asm volatile("cp.async.commit_group;" ::: "memory");
}
__device__ __forceinline__ uint32_t lds32(uint32_t addr) {
    uint32_t v;
    asm volatile("ld.shared.b32 %0, [%1];" : "=r"(v) : "r"(addr));
    return v;
}
__device__ __forceinline__ void ldm4(uint32_t* r, uint32_t addr) {
    asm volatile("ldmatrix.sync.aligned.m8n8.x4.shared.b16 {%0,%1,%2,%3}, [%4];"
                 : "=r"(r[0]), "=r"(r[1]), "=r"(r[2]), "=r"(r[3]) : "r"(addr));
}
__device__ __forceinline__ uint32_t hmul2u(uint32_t a, uint32_t b) {
    __half2 r = __hmul2(*(__half2*)&a, *(__half2*)&b);
    return *(uint32_t*)&r;
}
__device__ __forceinline__ void mma16816(float* c, const uint32_t* a,
                                         uint32_t b0, uint32_t b1) {
    asm volatile(
        "mma.sync.aligned.m16n8k16.row.col.f32.f16.f16.f32 "
        "{%0,%1,%2,%3}, {%4,%5,%6,%7}, {%8,%9}, {%0,%1,%2,%3};"
        : "+f"(c[0]), "+f"(c[1]), "+f"(c[2]), "+f"(c[3])
        : "r"(a[0]), "r"(a[1]), "r"(a[2]), "r"(a[3]), "r"(b0), "r"(b1));
}

// ---------------- prep ----------------
__global__ void prep_H(const float* __restrict__ X, const float* __restrict__ W,
                       const float* __restrict__ bias) {
    int id = blockIdx.x * blockDim.x + threadIdx.x;  // 131072
    int i = id >> 6, f = id & 63;
    float s = 0.f;
#pragma unroll 8
    for (int c = 0; c < FIN; c++) s += X[i * FIN + c] * W[c * FOUT + f];
    s += bias[f];
    g_H[id] = s;
    g_HhT[f * NN + i] = __float2half_rn(s);
}
__global__ void prep_A(const float* __restrict__ A) {
    size_t id = (size_t)blockIdx.x * blockDim.x + threadIdx.x;
    float2 v = ((const float2*)A)[id];
    ((__half2*)g_Ah)[id] = __floats2half2_rn(v.x, v.y);
}
// tiled transpose + fp16 convert: g_mhT[k][i] = fp16(mh[i][k])
__global__ void prep_mhT(const float* __restrict__ mh) {
    __shared__ float t[32][33];
    const int bx = blockIdx.x * 32, by = blockIdx.y * 32;  // bx: k, by: i
    const int tx = threadIdx.x & 31, ty = threadIdx.x >> 5;
#pragma unroll
    for (int y = ty; y < 32; y += 8)
        t[y][tx] = mh[(size_t)(by + y) * NN + bx + tx];
    __syncthreads();
#pragma unroll
    for (int o = 0; o < 2; o++) {
        int idx = threadIdx.x + o * 256;
        int kr = idx >> 4, ip = idx & 15;
        __half2 v = __floats2half2_rn(t[ip * 2][kr], t[ip * 2 + 1][kr]);
        *(__half2*)&g_mhT[(size_t)(bx + kr) * NN + by + ip * 2] = v;
    }
}
__global__ void zero_out(float* __restrict__ out) {
    out[blockIdx.x * blockDim.x + threadIdx.x] = 0.f;
}

// ---------------- main (persistent) ----------------
// grid = #SMs, 256 threads = 8 warps laid out 2 (j) x 4 (k).
__global__ void __launch_bounds__(256, 1)
interaction_main(const float* __restrict__ mf, float* __restrict__ out) {
    extern __shared__ char smem[];
    const uint32_t sb = smem_to_u32(smem);
    const int tid = threadIdx.x;
    const int lane = tid & 31, wid = tid >> 5;
    const int g = lane >> 2, tg = lane & 3;
    const int jbw = (wid & 1) * 64;    // warp j block (4 x m16)
    const int kbw = (wid >> 1) * 16;   // warp k block (2 x n8)
    const int cta = blockIdx.x, nsm = gridDim.x;

    const int ntiles = (cta < NTILES) ? ((NTILES - 1 - cta) / nsm + 1) : 0;
    const int total = ntiles * CPT;    // total chunks for this CTA
    if (total == 0) return;

    // B ldmatrix lane mapping (validated R5): tile id = lane>>3,
    // bit0 -> i-half (col +16B), bit1 -> n8 tile (row group +8)
    const int btl = lane >> 3;
    const int bn = kbw + ((btl >> 1) & 1) * 8 + (lane & 7);
    const uint32_t bcol0 = (uint32_t)((btl & 1) * 16);

    // ---- chunk loader: tile decoded from global chunk index ----
    auto issue = [&](int gc) {
        if (gc >= total) return;
        const int s = gc >> 4, c = gc & 15;
        const int t = cta + s * nsm;
        const int jb = (t >> 9) * JT;
        const int kb = ((t >> 4) & 31) * KT;
        const int ff = (t & 15) * FB;
        const uint32_t base = sb + (uint32_t)(gc & 3) * STAGE;
        const int ibase = c * IC;
#pragma unroll
        for (int o = 0; o < 8; o++) {
            int idx = tid + o * 256, j = idx >> 4, cc = idx & 15;
            cp16(base + ST_A + j * 256 + ((cc * 16) ^ ((j & 7) * 16)),
                 g_Ah + (size_t)(jb + j) * NN + ibase + cc * 8);
        }
#pragma unroll
        for (int o = 0; o < 4; o++) {
            int idx = tid + o * 256, n = idx >> 4, cc = idx & 15;
            cp16(base + ST_MH + n * 256 + ((cc * 16) ^ ((n & 7) * 16)),
                 g_mhT + (size_t)(kb + n) * NN + ibase + cc * 8);
        }
        if (tid < 64) {
            int f = tid >> 4, cc = tid & 15;
            cp16(base + ST_H + f * 256 + cc * 16,
                 g_HhT + (size_t)(ff + f) * NN + ibase + cc * 8);
        }
        if (c == 0 && tid < 64) {
            // Hk [64][4] fp32 for tile s, parity buffer s&1. Race-free: the
            // epilogue reading buffer (s-2)&1 completed >=15 barriers earlier.
            cp16(sb + SM_HK + (uint32_t)(s & 1) * 1024 + tid * 16,
                 g_H + (kb + tid) * FOUT + ff);
        }
        cp_commit();
    };

    issue(0);
    issue(1);

    float acc[FB][4][2][4];            // 128 regs
    for (int s = 0; s < ntiles; s++) {
        const int t = cta + s * nsm;
        const int jbase = (t >> 9) * JT;
        const int kb0 = ((t >> 4) & 31) * KT;
        const int f0 = (t & 15) * FB;

#pragma unroll
        for (int f = 0; f < FB; f++)
#pragma unroll
            for (int mt = 0; mt < 4; mt++)
#pragma unroll
                for (int nt = 0; nt < 2; nt++)
#pragma unroll
                    for (int e = 0; e < 4; e++) acc[f][mt][nt][e] = 0.f;

        for (int c = 0; c < CPT; c++) {
            const int gc = s * CPT + c;
            // R7-style: prefetch FIRST so its latency overlaps the wait.
            // Race-free with 4 stages: writer stage (gc+2)&3; the slowest
            // warp (past barrier gc-1) reads at most stage (gc-1)&3 -- the
            // four stages gc-1..gc+2 are distinct mod 4.
            if (gc + 2 < total) {
                issue(gc + 2);
                asm volatile("cp.async.wait_group 2;" ::: "memory");
            } else if (gc + 1 < total) {
                asm volatile("cp.async.wait_group 1;" ::: "memory");
            } else {
                asm volatile("cp.async.wait_group 0;" ::: "memory");
            }
            __syncthreads();   // chunk gc visible; all warps aligned

            const int st = gc & 3;
            const uint32_t abase = sb + (uint32_t)st * STAGE + ST_A;
            const uint32_t mbase = sb + (uint32_t)st * STAGE + ST_MH;
            const uint32_t hbase = sb + (uint32_t)st * STAGE + ST_H;

#pragma unroll 4
            for (int ks = 0; ks < 8; ks++) {
                uint32_t a[4][4];
#pragma unroll
                for (int mt = 0; mt < 4; mt++) {
                    int jr = jbw + mt * 16 + (lane & 15);
                    ldm4(a[mt], abase + jr * 256 +
                                   ((((lane >> 4) * 16) + ks * 32) ^ ((jr & 7) * 16)));
                }
                uint32_t bfr[4];
                ldm4(bfr, mbase + bn * 256 + ((ks * 32 + bcol0) ^ ((bn & 7) * 16)));

#pragma unroll
                for (int f = 0; f < FB; f++) {
                    uint32_t hA = lds32(hbase + f * 256 + ks * 32 + tg * 4);
                    uint32_t hB = lds32(hbase + f * 256 + ks * 32 + tg * 4 + 16);
                    uint32_t b00 = hmul2u(bfr[0], hA);
                    uint32_t b01 = hmul2u(bfr[1], hB);
                    uint32_t b10 = hmul2u(bfr[2], hA);
                    uint32_t b11 = hmul2u(bfr[3], hB);
#pragma unroll
                    for (int mt = 0; mt < 4; mt++) {
                        mma16816(acc[f][mt][0], a[mt], b00, b01);
                        mma16816(acc[f][mt][1], a[mt], b10, b11);
                    }
                }
            }
        }

        // ---- epilogue (no barrier): float2 mf LDG (L2-hot), Hk parity smem
        const float* Hks = (const float*)(smem + SM_HK + (size_t)(s & 1) * 1024);
#pragma unroll
        for (int mt = 0; mt < 4; mt++)
#pragma unroll
            for (int h2 = 0; h2 < 2; h2++) {
                const int j = jbw + mt * 16 + g + 8 * h2;
                float s4[FB] = {0.f, 0.f, 0.f, 0.f};
#pragma unroll
                for (int nt = 0; nt < 2; nt++) {
                    const int k0 = kbw + nt * 8 + tg * 2;
                    const float2 mp =
                        *(const float2*)&mf[(size_t)(jbase + j) * NN + kb0 + k0];
#pragma unroll
                    for (int e = 0; e < 2; e++) {
                        const float mv = e ? mp.y : mp.x;
                        const float4 hk = *(const float4*)&Hks[(k0 + e) * 4];
                        s4[0] += acc[0][mt][nt][h2 * 2 + e] * mv * hk.x;
                        s4[1] += acc[1][mt][nt][h2 * 2 + e] * mv * hk.y;
                        s4[2] += acc[2][mt][nt][h2 * 2 + e] * mv * hk.z;
                        s4[3] += acc[3][mt][nt][h2 * 2 + e] * mv * hk.w;
                    }
                }
#pragma unroll
                for (int f = 0; f < FB; f++) {
                    float v = s4[f];
                    v += __shfl_xor_sync(0xffffffffu, v, 1);
                    v += __shfl_xor_sync(0xffffffffu, v, 2);
                    if (tg == 0)
                        atomicAdd(&out[(size_t)(jbase + j) * FOUT + f0 + f], v);
                }
            }
    }
}

// ---------------- launch ----------------
extern "C" void kernel_launch(void* const* d_in, const int* in_sizes, int n_in,
                              void* d_out, int out_size) {
    const float* X  = (const float*)d_in[0];
    const float* A  = (const float*)d_in[1];
    const float* mf = (const float*)d_in[2];
    const float* mh = (const float*)d_in[3];
    const float* W  = (const float*)d_in[4];
    const float* b  = (const float*)d_in[5];
    float* out = (float*)d_out;

    int dev = 0, nsm = 148;
    cudaGetDevice(&dev);
    cudaDeviceGetAttribute(&nsm, cudaDevAttrMultiProcessorCount, dev);

    cudaFuncSetAttribute(interaction_main,
                         cudaFuncAttributeMaxDynamicSharedMemorySize, SMEM_TOTAL);

    prep_H<<<256, 512>>>(X, W, b);
    prep_A<<<4096, 512>>>(A);
    prep_mhT<<<dim3(64, 64), 256>>>(mh);
    zero_out<<<256, 512>>>(out);
    interaction_main<<<nsm, 256, SMEM_TOTAL>>>(mf, out);
}